// round 1
// baseline (speedup 1.0000x reference)
#include <cuda_runtime.h>

// Problem constants
#define L_SEQ  2048
#define DMODEL 1024
#define NHEADS 16
#define DKH    64
#define NB     4
#define MROWS  (NB * L_SEQ)   // 8192

// Scratch: __device__ globals (no runtime allocation allowed).
// Layouts:
//   g_q/g_k/g_v : [B][H][L][DK]   (head-major for attention)
//   g_o         : [B][L][H*DK] == [8192][1024] row-major (ready for out-proj)
__device__ float g_q[(size_t)NB * NHEADS * L_SEQ * DKH];
__device__ float g_k[(size_t)NB * NHEADS * L_SEQ * DKH];
__device__ float g_v[(size_t)NB * NHEADS * L_SEQ * DKH];
__device__ float g_o[(size_t)MROWS * DMODEL];

// ---------------------------------------------------------------------------
// GEMM:  C[m,n] = sum_k A[m,k] * W[n,k] + bias[n]
// A: [M=8192, K=1024] row-major, W: [N=1024, K=1024] row-major (i.e. X @ W^T)
// scatter==0 : C row-major [M, N]
// scatter==1 : C scattered to [B][H][L][DK]  (m=(b,l), n=(h,d))
// Tile: 128x128, BK=16, 256 threads, 8x8 microtile per thread.
// ---------------------------------------------------------------------------
__global__ __launch_bounds__(256) void gemm_nt_kernel(
    const float* __restrict__ A, const float* __restrict__ W,
    const float* __restrict__ bias, float* __restrict__ C, int scatter)
{
    const int K = DMODEL;
    const int N = DMODEL;
    __shared__ float As[16][128];
    __shared__ float Bs[16][128];

    const int tid = threadIdx.x;
    const int tx = tid & 15;
    const int ty = tid >> 4;
    const int m0 = blockIdx.y * 128;
    const int n0 = blockIdx.x * 128;

    float acc[8][8];
#pragma unroll
    for (int i = 0; i < 8; ++i)
#pragma unroll
        for (int j = 0; j < 8; ++j) acc[i][j] = 0.0f;

    for (int k0 = 0; k0 < K; k0 += 16) {
        // Load A and W tiles (transposed into [k][m] / [k][n] layout).
#pragma unroll
        for (int p = 0; p < 2; ++p) {
            int fi  = tid + p * 256;      // float4 id: 512 per tile
            int row = fi >> 2;            // 0..127
            int c4  = (fi & 3) << 2;      // 0,4,8,12
            float4 av = *(const float4*)(A + (size_t)(m0 + row) * K + k0 + c4);
            As[c4 + 0][row] = av.x; As[c4 + 1][row] = av.y;
            As[c4 + 2][row] = av.z; As[c4 + 3][row] = av.w;
            float4 wv = *(const float4*)(W + (size_t)(n0 + row) * K + k0 + c4);
            Bs[c4 + 0][row] = wv.x; Bs[c4 + 1][row] = wv.y;
            Bs[c4 + 2][row] = wv.z; Bs[c4 + 3][row] = wv.w;
        }
        __syncthreads();

#pragma unroll
        for (int kk = 0; kk < 16; ++kk) {
            float a[8], b[8];
            *(float4*)&a[0] = *(const float4*)&As[kk][ty * 8];
            *(float4*)&a[4] = *(const float4*)&As[kk][ty * 8 + 4];
            *(float4*)&b[0] = *(const float4*)&Bs[kk][tx * 8];
            *(float4*)&b[4] = *(const float4*)&Bs[kk][tx * 8 + 4];
#pragma unroll
            for (int i = 0; i < 8; ++i)
#pragma unroll
                for (int j = 0; j < 8; ++j)
                    acc[i][j] += a[i] * b[j];
        }
        __syncthreads();
    }

    // Epilogue
    const int ncol = n0 + tx * 8;
    float bvals[8];
#pragma unroll
    for (int j = 0; j < 8; ++j) bvals[j] = bias[ncol + j];

#pragma unroll
    for (int i = 0; i < 8; ++i) {
        int m = m0 + ty * 8 + i;
        float out[8];
#pragma unroll
        for (int j = 0; j < 8; ++j) out[j] = acc[i][j] + bvals[j];

        size_t base;
        if (scatter) {
            int b    = m >> 11;          // m / L_SEQ
            int lpos = m & (L_SEQ - 1);
            int h    = ncol >> 6;        // ncol / DKH  (8-wide chunk never crosses a head)
            int d    = ncol & 63;
            base = (((size_t)(b * NHEADS + h)) * L_SEQ + lpos) * DKH + d;
        } else {
            base = (size_t)m * N + ncol;
        }
        *(float4*)&C[base + 0] = make_float4(out[0], out[1], out[2], out[3]);
        *(float4*)&C[base + 4] = make_float4(out[4], out[5], out[6], out[7]);
    }
}

// ---------------------------------------------------------------------------
// Causal flash attention, fp32.
// Grid: (L/64, B*H). Block: 256 threads.
// Per CTA: Q block of 64 rows of one (b,h); loop over K/V blocks of 32.
// Online softmax; O accumulated in registers (4 rows x 4 cols per thread).
// ---------------------------------------------------------------------------
__global__ __launch_bounds__(256) void attn_kernel()
{
    __shared__ float Qs[64][68];   // [d][i]  (transposed), pad to 68
    __shared__ float Ks[64][36];   // [d][j]  (transposed), pad to 36
    __shared__ float Vs[32][64];   // [j][d]  natural
    __shared__ float Ps[32][68];   // [j][i]  (transposed P)

    const int tid = threadIdx.x;
    const int tx = tid & 15;
    const int ty = tid >> 4;
    const int qb = blockIdx.x;
    const int bh = blockIdx.y;

    const float* qptr = g_q + ((size_t)bh * L_SEQ + qb * 64) * DKH;
    const float* kbase = g_k + (size_t)bh * L_SEQ * DKH;
    const float* vbase = g_v + (size_t)bh * L_SEQ * DKH;

    // Load Q tile transposed: 64 rows x 64 d = 1024 float4
#pragma unroll
    for (int p = 0; p < 4; ++p) {
        int fi  = tid + p * 256;
        int row = fi >> 4;           // 0..63
        int c4  = (fi & 15) << 2;    // 0..60
        float4 v4 = *(const float4*)(qptr + (size_t)row * DKH + c4);
        Qs[c4 + 0][row] = v4.x; Qs[c4 + 1][row] = v4.y;
        Qs[c4 + 2][row] = v4.z; Qs[c4 + 3][row] = v4.w;
    }

    const int i0 = ty * 4;   // S rows / O rows
    const int j0 = tx * 2;   // S cols
    const int d0 = tx * 4;   // O cols

    float mrow[4], lrow[4], o[4][4];
#pragma unroll
    for (int ii = 0; ii < 4; ++ii) {
        mrow[ii] = -1e30f;
        lrow[ii] = 0.0f;
#pragma unroll
        for (int dd = 0; dd < 4; ++dd) o[ii][dd] = 0.0f;
    }

    const float scale = 0.125f;     // 1/sqrt(64)
    const int nkb = 2 * qb + 2;     // causal: k-blocks of 32 up to qb*64+63

    for (int kb = 0; kb < nkb; ++kb) {
        __syncthreads();   // previous iteration's reads of Ks/Vs/Ps complete
        // Load K (transposed) and V (natural): 32 x 64 each = 512 float4 each
#pragma unroll
        for (int p = 0; p < 2; ++p) {
            int fi  = tid + p * 256;
            int row = fi >> 4;          // 0..31
            int c4  = (fi & 15) << 2;
            size_t goff = (size_t)(kb * 32 + row) * DKH + c4;
            float4 kv = *(const float4*)(kbase + goff);
            Ks[c4 + 0][row] = kv.x; Ks[c4 + 1][row] = kv.y;
            Ks[c4 + 2][row] = kv.z; Ks[c4 + 3][row] = kv.w;
            float4 vv = *(const float4*)(vbase + goff);
            *(float4*)&Vs[row][c4] = vv;
        }
        __syncthreads();

        // S = Q @ K^T  (64x32), each thread 4x2
        float s[4][2];
#pragma unroll
        for (int ii = 0; ii < 4; ++ii) { s[ii][0] = 0.0f; s[ii][1] = 0.0f; }
#pragma unroll 4
        for (int d = 0; d < 64; ++d) {
            float4 qv = *(const float4*)&Qs[d][i0];
            float2 kv = *(const float2*)&Ks[d][j0];
            s[0][0] += qv.x * kv.x;  s[0][1] += qv.x * kv.y;
            s[1][0] += qv.y * kv.x;  s[1][1] += qv.y * kv.y;
            s[2][0] += qv.z * kv.x;  s[2][1] += qv.z * kv.y;
            s[3][0] += qv.w * kv.x;  s[3][1] += qv.w * kv.y;
        }

        // Scale + causal mask (only the last two k-blocks overlap the diagonal)
        const bool diag = (kb >= 2 * qb);
#pragma unroll
        for (int ii = 0; ii < 4; ++ii) {
#pragma unroll
            for (int jj = 0; jj < 2; ++jj) {
                float v = s[ii][jj] * scale;
                if (diag) {
                    int jg = kb * 32 + j0 + jj;
                    int ig = qb * 64 + i0 + ii;
                    if (jg > ig) v = -1e30f;
                }
                s[ii][jj] = v;
            }
        }

        // Online softmax per row (reduce over the 16 tx lanes of this half-warp)
#pragma unroll
        for (int ii = 0; ii < 4; ++ii) {
            float rm = fmaxf(s[ii][0], s[ii][1]);
#pragma unroll
            for (int off = 8; off > 0; off >>= 1)
                rm = fmaxf(rm, __shfl_xor_sync(0xffffffffu, rm, off));
            float mn   = fmaxf(mrow[ii], rm);
            float corr = __expf(mrow[ii] - mn);
            float p0 = __expf(s[ii][0] - mn);
            float p1 = __expf(s[ii][1] - mn);
            float rs = p0 + p1;
#pragma unroll
            for (int off = 8; off > 0; off >>= 1)
                rs += __shfl_xor_sync(0xffffffffu, rs, off);
            lrow[ii] = lrow[ii] * corr + rs;
            mrow[ii] = mn;
#pragma unroll
            for (int dd = 0; dd < 4; ++dd) o[ii][dd] *= corr;
            Ps[j0 + 0][i0 + ii] = p0;
            Ps[j0 + 1][i0 + ii] = p1;
        }
        __syncthreads();

        // O += P @ V   (each thread: rows i0..i0+3, cols d0..d0+3)
#pragma unroll 2
        for (int j = 0; j < 32; ++j) {
            float4 pv = *(const float4*)&Ps[j][i0];
            float4 vv = *(const float4*)&Vs[j][d0];
            o[0][0] += pv.x * vv.x; o[0][1] += pv.x * vv.y; o[0][2] += pv.x * vv.z; o[0][3] += pv.x * vv.w;
            o[1][0] += pv.y * vv.x; o[1][1] += pv.y * vv.y; o[1][2] += pv.y * vv.z; o[1][3] += pv.y * vv.w;
            o[2][0] += pv.z * vv.x; o[2][1] += pv.z * vv.y; o[2][2] += pv.z * vv.z; o[2][3] += pv.z * vv.w;
            o[3][0] += pv.w * vv.x; o[3][1] += pv.w * vv.y; o[3][2] += pv.w * vv.z; o[3][3] += pv.w * vv.w;
        }
    }

    // Normalize and write O to [B][L][H*DK]
    const int b = bh >> 4;
    const int h = bh & 15;
#pragma unroll
    for (int ii = 0; ii < 4; ++ii) {
        float inv = 1.0f / lrow[ii];
        int row = qb * 64 + i0 + ii;
        size_t base = ((size_t)(b * L_SEQ + row)) * DMODEL + h * DKH + d0;
        *(float4*)&g_o[base] =
            make_float4(o[ii][0] * inv, o[ii][1] * inv, o[ii][2] * inv, o[ii][3] * inv);
    }
}

// ---------------------------------------------------------------------------
// kernel_launch
// ---------------------------------------------------------------------------
extern "C" void kernel_launch(void* const* d_in, const int* in_sizes, int n_in,
                              void* d_out, int out_size)
{
    const float* Q = (const float*)d_in[0];
    const float* K = (const float*)d_in[1];
    const float* V = (const float*)d_in[2];

    // attn_mask (L*L int32) is either at index 3 (setup_inputs order) or last
    // (function-arg order). Detect by size; weights follow Q,K,V(,mask).
    int wb = 3;
    if (n_in >= 12 && in_sizes[3] == L_SEQ * L_SEQ) wb = 4;

    const float* Wq = (const float*)d_in[wb + 0];
    const float* bq = (const float*)d_in[wb + 1];
    const float* Wk = (const float*)d_in[wb + 2];
    const float* bk = (const float*)d_in[wb + 3];
    const float* Wv = (const float*)d_in[wb + 4];
    const float* bv = (const float*)d_in[wb + 5];
    const float* Wo = (const float*)d_in[wb + 6];
    const float* bo = (const float*)d_in[wb + 7];

    float *qp, *kp, *vp, *op;
    cudaGetSymbolAddress((void**)&qp, g_q);
    cudaGetSymbolAddress((void**)&kp, g_k);
    cudaGetSymbolAddress((void**)&vp, g_v);
    cudaGetSymbolAddress((void**)&op, g_o);

    dim3 gg(DMODEL / 128, MROWS / 128);   // (8, 64)

    gemm_nt_kernel<<<gg, 256>>>(Q, Wq, bq, qp, 1);
    gemm_nt_kernel<<<gg, 256>>>(K, Wk, bk, kp, 1);
    gemm_nt_kernel<<<gg, 256>>>(V, Wv, bv, vp, 1);

    attn_kernel<<<dim3(L_SEQ / 64, NB * NHEADS), 256>>>();

    gemm_nt_kernel<<<gg, 256>>>(op, Wo, bo, (float*)d_out, 0);
}

// round 2
// speedup vs baseline: 1.5896x; 1.5896x over previous
#include <cuda_runtime.h>
#include <cstdint>

// Problem constants
#define L_SEQ  2048
#define DMODEL 1024
#define NHEADS 16
#define DKH    64
#define NB     4
#define MROWS  (NB * L_SEQ)   // 8192

// Scratch: __device__ globals (no runtime allocation allowed).
//   g_q/g_k/g_v : [B][H][L][DK]   (head-major for attention)
//   g_o         : [B][L][H*DK] == [8192][1024] row-major (ready for out-proj)
__device__ float g_q[(size_t)NB * NHEADS * L_SEQ * DKH];
__device__ float g_k[(size_t)NB * NHEADS * L_SEQ * DKH];
__device__ float g_v[(size_t)NB * NHEADS * L_SEQ * DKH];
__device__ float g_o[(size_t)MROWS * DMODEL];

// ---------------------------------------------------------------------------
// tf32 helpers
// ---------------------------------------------------------------------------
__device__ __forceinline__ uint32_t f2tf(float f) {
    uint32_t u;
    asm("cvt.rna.tf32.f32 %0, %1;" : "=r"(u) : "f"(f));
    return u;
}

__device__ __forceinline__ void mma_tf32(float c[4], const uint32_t a[4],
                                         const uint32_t b[2]) {
    asm volatile(
        "mma.sync.aligned.m16n8k8.row.col.f32.tf32.tf32.f32 "
        "{%0,%1,%2,%3}, {%4,%5,%6,%7}, {%8,%9}, {%0,%1,%2,%3};\n"
        : "+f"(c[0]), "+f"(c[1]), "+f"(c[2]), "+f"(c[3])
        : "r"(a[0]), "r"(a[1]), "r"(a[2]), "r"(a[3]), "r"(b[0]), "r"(b[1]));
}

// ---------------------------------------------------------------------------
// Tensor-core GEMM:  C[m,n] = sum_k A[m,k] * W[n,k] + bias[n]   (tf32 MMA)
// A: [M=8192, K=1024] row-major, W: [N=1024, K=1024] row-major.
// scatter==0 : C row-major [M, N]
// scatter==1 : C scattered to [B][H][L][DK]
// CTA tile 128x128, BK=16, 256 threads = 8 warps; warp tile 64x32 (2x4 grid).
// ---------------------------------------------------------------------------
__global__ __launch_bounds__(256) void gemm_tf32_kernel(
    const float* __restrict__ A, const float* __restrict__ W,
    const float* __restrict__ bias, float* __restrict__ C, int scatter)
{
    const int K = DMODEL;
    const int N = DMODEL;
    // natural [m][k] / [n][k] layouts, k padded 16->20 (conflict-free frags)
    __shared__ __align__(16) uint32_t As[128][20];
    __shared__ __align__(16) uint32_t Bs[128][20];

    const int tid  = threadIdx.x;
    const int lane = tid & 31;
    const int warp = tid >> 5;
    const int g    = lane >> 2;     // group 0..7
    const int tig  = lane & 3;      // 0..3
    const int wm   = (warp & 1) * 64;
    const int wn   = (warp >> 1) * 32;
    const int m0   = blockIdx.y * 128;
    const int n0   = blockIdx.x * 128;

    float c[4][4][4];
#pragma unroll
    for (int mt = 0; mt < 4; ++mt)
#pragma unroll
        for (int nt = 0; nt < 4; ++nt)
#pragma unroll
            for (int i = 0; i < 4; ++i) c[mt][nt][i] = 0.0f;

    // global load pattern: 2 float4 per tile per thread
    const int lrow = tid >> 2;          // 0..63
    const int lc4  = (tid & 3) << 2;    // 0,4,8,12

    float4 ra[2], rb[2];
#define LOADG(k0)                                                              \
    do {                                                                       \
        ra[0] = *(const float4*)(A + (size_t)(m0 + lrow) * K + (k0) + lc4);    \
        ra[1] = *(const float4*)(A + (size_t)(m0 + lrow + 64) * K + (k0) + lc4);\
        rb[0] = *(const float4*)(W + (size_t)(n0 + lrow) * K + (k0) + lc4);    \
        rb[1] = *(const float4*)(W + (size_t)(n0 + lrow + 64) * K + (k0) + lc4);\
    } while (0)

    LOADG(0);

    for (int k0 = 0; k0 < K; k0 += 16) {
        __syncthreads();
        {   // store (converted to tf32) into smem as uint4
            uint4 t;
            t.x = f2tf(ra[0].x); t.y = f2tf(ra[0].y);
            t.z = f2tf(ra[0].z); t.w = f2tf(ra[0].w);
            *(uint4*)&As[lrow][lc4] = t;
            t.x = f2tf(ra[1].x); t.y = f2tf(ra[1].y);
            t.z = f2tf(ra[1].z); t.w = f2tf(ra[1].w);
            *(uint4*)&As[lrow + 64][lc4] = t;
            t.x = f2tf(rb[0].x); t.y = f2tf(rb[0].y);
            t.z = f2tf(rb[0].z); t.w = f2tf(rb[0].w);
            *(uint4*)&Bs[lrow][lc4] = t;
            t.x = f2tf(rb[1].x); t.y = f2tf(rb[1].y);
            t.z = f2tf(rb[1].z); t.w = f2tf(rb[1].w);
            *(uint4*)&Bs[lrow + 64][lc4] = t;
        }
        __syncthreads();

        if (k0 + 16 < K) LOADG(k0 + 16);

#pragma unroll
        for (int ks = 0; ks < 16; ks += 8) {
            uint32_t af[4][4], bf[4][2];
#pragma unroll
            for (int mt = 0; mt < 4; ++mt) {
                const int mr = wm + mt * 16;
                af[mt][0] = As[mr + g][ks + tig];
                af[mt][1] = As[mr + g + 8][ks + tig];
                af[mt][2] = As[mr + g][ks + tig + 4];
                af[mt][3] = As[mr + g + 8][ks + tig + 4];
            }
#pragma unroll
            for (int nt = 0; nt < 4; ++nt) {
                const int nr = wn + nt * 8 + g;
                bf[nt][0] = Bs[nr][ks + tig];
                bf[nt][1] = Bs[nr][ks + tig + 4];
            }
#pragma unroll
            for (int mt = 0; mt < 4; ++mt)
#pragma unroll
                for (int nt = 0; nt < 4; ++nt)
                    mma_tf32(c[mt][nt], af[mt], bf[nt]);
        }
    }
#undef LOADG

    // Epilogue: c0/c1 -> (row g, cols 2tig,2tig+1); c2/c3 -> row g+8
#pragma unroll
    for (int nt = 0; nt < 4; ++nt) {
        const int ncol = n0 + wn + nt * 8 + 2 * tig;
        const float b0 = bias[ncol];
        const float b1 = bias[ncol + 1];
#pragma unroll
        for (int mt = 0; mt < 4; ++mt) {
#pragma unroll
            for (int half = 0; half < 2; ++half) {
                const int m = m0 + wm + mt * 16 + g + half * 8;
                size_t base;
                if (scatter) {
                    const int b    = m >> 11;
                    const int lpos = m & (L_SEQ - 1);
                    const int h    = ncol >> 6;
                    const int d    = ncol & 63;
                    base = (((size_t)(b * NHEADS + h)) * L_SEQ + lpos) * DKH + d;
                } else {
                    base = (size_t)m * N + ncol;
                }
                *(float2*)&C[base] = make_float2(c[mt][nt][half * 2 + 0] + b0,
                                                 c[mt][nt][half * 2 + 1] + b1);
            }
        }
    }
}

// ---------------------------------------------------------------------------
// Causal flash attention, fp32 (unchanged from passing R1 kernel).
// Grid: (L/64, B*H). Block: 256 threads.
// ---------------------------------------------------------------------------
__global__ __launch_bounds__(256) void attn_kernel()
{
    __shared__ float Qs[64][68];
    __shared__ float Ks[64][36];
    __shared__ float Vs[32][64];
    __shared__ float Ps[32][68];

    const int tid = threadIdx.x;
    const int tx = tid & 15;
    const int ty = tid >> 4;
    const int qb = blockIdx.x;
    const int bh = blockIdx.y;

    const float* qptr  = g_q + ((size_t)bh * L_SEQ + qb * 64) * DKH;
    const float* kbase = g_k + (size_t)bh * L_SEQ * DKH;
    const float* vbase = g_v + (size_t)bh * L_SEQ * DKH;

#pragma unroll
    for (int p = 0; p < 4; ++p) {
        int fi  = tid + p * 256;
        int row = fi >> 4;
        int c4  = (fi & 15) << 2;
        float4 v4 = *(const float4*)(qptr + (size_t)row * DKH + c4);
        Qs[c4 + 0][row] = v4.x; Qs[c4 + 1][row] = v4.y;
        Qs[c4 + 2][row] = v4.z; Qs[c4 + 3][row] = v4.w;
    }

    const int i0 = ty * 4;
    const int j0 = tx * 2;
    const int d0 = tx * 4;

    float mrow[4], lrow[4], o[4][4];
#pragma unroll
    for (int ii = 0; ii < 4; ++ii) {
        mrow[ii] = -1e30f;
        lrow[ii] = 0.0f;
#pragma unroll
        for (int dd = 0; dd < 4; ++dd) o[ii][dd] = 0.0f;
    }

    const float scale = 0.125f;
    const int nkb = 2 * qb + 2;

    for (int kb = 0; kb < nkb; ++kb) {
        __syncthreads();
#pragma unroll
        for (int p = 0; p < 2; ++p) {
            int fi  = tid + p * 256;
            int row = fi >> 4;
            int c4  = (fi & 15) << 2;
            size_t goff = (size_t)(kb * 32 + row) * DKH + c4;
            float4 kv = *(const float4*)(kbase + goff);
            Ks[c4 + 0][row] = kv.x; Ks[c4 + 1][row] = kv.y;
            Ks[c4 + 2][row] = kv.z; Ks[c4 + 3][row] = kv.w;
            float4 vv = *(const float4*)(vbase + goff);
            *(float4*)&Vs[row][c4] = vv;
        }
        __syncthreads();

        float s[4][2];
#pragma unroll
        for (int ii = 0; ii < 4; ++ii) { s[ii][0] = 0.0f; s[ii][1] = 0.0f; }
#pragma unroll 4
        for (int d = 0; d < 64; ++d) {
            float4 qv = *(const float4*)&Qs[d][i0];
            float2 kv = *(const float2*)&Ks[d][j0];
            s[0][0] += qv.x * kv.x;  s[0][1] += qv.x * kv.y;
            s[1][0] += qv.y * kv.x;  s[1][1] += qv.y * kv.y;
            s[2][0] += qv.z * kv.x;  s[2][1] += qv.z * kv.y;
            s[3][0] += qv.w * kv.x;  s[3][1] += qv.w * kv.y;
        }

        const bool diag = (kb >= 2 * qb);
#pragma unroll
        for (int ii = 0; ii < 4; ++ii) {
#pragma unroll
            for (int jj = 0; jj < 2; ++jj) {
                float v = s[ii][jj] * scale;
                if (diag) {
                    int jg = kb * 32 + j0 + jj;
                    int ig = qb * 64 + i0 + ii;
                    if (jg > ig) v = -1e30f;
                }
                s[ii][jj] = v;
            }
        }

#pragma unroll
        for (int ii = 0; ii < 4; ++ii) {
            float rm = fmaxf(s[ii][0], s[ii][1]);
#pragma unroll
            for (int off = 8; off > 0; off >>= 1)
                rm = fmaxf(rm, __shfl_xor_sync(0xffffffffu, rm, off));
            float mn   = fmaxf(mrow[ii], rm);
            float corr = __expf(mrow[ii] - mn);
            float p0 = __expf(s[ii][0] - mn);
            float p1 = __expf(s[ii][1] - mn);
            float rs = p0 + p1;
#pragma unroll
            for (int off = 8; off > 0; off >>= 1)
                rs += __shfl_xor_sync(0xffffffffu, rs, off);
            lrow[ii] = lrow[ii] * corr + rs;
            mrow[ii] = mn;
#pragma unroll
            for (int dd = 0; dd < 4; ++dd) o[ii][dd] *= corr;
            Ps[j0 + 0][i0 + ii] = p0;
            Ps[j0 + 1][i0 + ii] = p1;
        }
        __syncthreads();

#pragma unroll 2
        for (int j = 0; j < 32; ++j) {
            float4 pv = *(const float4*)&Ps[j][i0];
            float4 vv = *(const float4*)&Vs[j][d0];
            o[0][0] += pv.x * vv.x; o[0][1] += pv.x * vv.y; o[0][2] += pv.x * vv.z; o[0][3] += pv.x * vv.w;
            o[1][0] += pv.y * vv.x; o[1][1] += pv.y * vv.y; o[1][2] += pv.y * vv.z; o[1][3] += pv.y * vv.w;
            o[2][0] += pv.z * vv.x; o[2][1] += pv.z * vv.y; o[2][2] += pv.z * vv.z; o[2][3] += pv.z * vv.w;
            o[3][0] += pv.w * vv.x; o[3][1] += pv.w * vv.y; o[3][2] += pv.w * vv.z; o[3][3] += pv.w * vv.w;
        }
    }

    const int b = bh >> 4;
    const int h = bh & 15;
#pragma unroll
    for (int ii = 0; ii < 4; ++ii) {
        float inv = 1.0f / lrow[ii];
        int row = qb * 64 + i0 + ii;
        size_t base = ((size_t)(b * L_SEQ + row)) * DMODEL + h * DKH + d0;
        *(float4*)&g_o[base] =
            make_float4(o[ii][0] * inv, o[ii][1] * inv, o[ii][2] * inv, o[ii][3] * inv);
    }
}

// ---------------------------------------------------------------------------
// kernel_launch
// ---------------------------------------------------------------------------
extern "C" void kernel_launch(void* const* d_in, const int* in_sizes, int n_in,
                              void* d_out, int out_size)
{
    const float* Q = (const float*)d_in[0];
    const float* K = (const float*)d_in[1];
    const float* V = (const float*)d_in[2];

    int wb = 3;
    if (n_in >= 12 && in_sizes[3] == L_SEQ * L_SEQ) wb = 4;

    const float* Wq = (const float*)d_in[wb + 0];
    const float* bq = (const float*)d_in[wb + 1];
    const float* Wk = (const float*)d_in[wb + 2];
    const float* bk = (const float*)d_in[wb + 3];
    const float* Wv = (const float*)d_in[wb + 4];
    const float* bv = (const float*)d_in[wb + 5];
    const float* Wo = (const float*)d_in[wb + 6];
    const float* bo = (const float*)d_in[wb + 7];

    float *qp, *kp, *vp, *op;
    cudaGetSymbolAddress((void**)&qp, g_q);
    cudaGetSymbolAddress((void**)&kp, g_k);
    cudaGetSymbolAddress((void**)&vp, g_v);
    cudaGetSymbolAddress((void**)&op, g_o);

    dim3 gg(DMODEL / 128, MROWS / 128);   // (8, 64)

    gemm_tf32_kernel<<<gg, 256>>>(Q, Wq, bq, qp, 1);
    gemm_tf32_kernel<<<gg, 256>>>(K, Wk, bk, kp, 1);
    gemm_tf32_kernel<<<gg, 256>>>(V, Wv, bv, vp, 1);

    attn_kernel<<<dim3(L_SEQ / 64, NB * NHEADS), 256>>>();

    gemm_tf32_kernel<<<gg, 256>>>(op, Wo, bo, (float*)d_out, 0);
}